// round 7
// baseline (speedup 1.0000x reference)
#include <cuda_runtime.h>

#define N    4096
#define K    10          // fused Jacobi steps per pass
#define TX   108         // output tile edge (TX + 2K = 128)
#define BW   128         // tile edge
#define NBLK 38          // ceil(4096 / 108)
#define NTH  512
#define NW   16          // warps per CTA
#define R    8           // rows per warp (NW * R == BW)

#define SCALE 0x1p-20f   // 0.25^K, exact power of two

// Scratch ping-pong buffer (allocation-free rule: __device__ global).
__device__ float g_buf[(size_t)N * N];

// Exchange buffer type: [step parity][top=0/bot=1][warp][col]
typedef float ExBuf[2][NW][BW];

template<bool EDGE>
__device__ __forceinline__ void run_steps(float4 (&u)[R], ExBuf* ex,
                                          int warp, int x4,
                                          int gx0, int gy0, int ybase) {
    float mx0 = 1.f, mx1 = 1.f, mx2 = 1.f, mx3 = 1.f;
    if (EDGE) {
        int g = gx0 + x4;
        mx0 = (g + 0 >= 1 && g + 0 <= N - 2) ? 1.f : 0.f;
        mx1 = (g + 1 >= 1 && g + 1 <= N - 2) ? 1.f : 0.f;
        mx2 = (g + 2 >= 1 && g + 2 <= N - 2) ? 1.f : 0.f;
        mx3 = (g + 3 >= 1 && g + 3 <= N - 2) ? 1.f : 0.f;
    }

    #pragma unroll 2
    for (int s = 0; s < K; s++) {
        const int par = s & 1;

        // publish own boundary rows (old values) for neighbor warps
        *(float4*)&ex[par][0][warp][x4] = u[0];       // my top row
        *(float4*)&ex[par][1][warp][x4] = u[R - 1];   // my bottom row
        __syncthreads();

        float4 above = make_float4(0.f, 0.f, 0.f, 0.f);
        if (warp > 0)
            above = *(const float4*)&ex[par][1][warp - 1][x4];
        float4 bedge = make_float4(0.f, 0.f, 0.f, 0.f);
        if (warp < NW - 1)
            bedge = *(const float4*)&ex[par][0][warp + 1][x4];

        #pragma unroll
        for (int r = 0; r < R; r++) {
            float4 cur = u[r];
            float4 dn  = (r < R - 1) ? u[r + 1] : bedge;
            float lf = __shfl_up_sync(0xffffffffu, cur.w, 1);
            float rt = __shfl_down_sync(0xffffffffu, cur.x, 1);

            // UNSCALED sum; global 0.25^K applied once in the epilogue.
            // Bit-exact vs per-step scaling (power-of-two factors).
            float4 nv;
            nv.x = (lf    + cur.y) + (above.x + dn.x);
            nv.y = (cur.x + cur.z) + (above.y + dn.y);
            nv.z = (cur.y + cur.w) + (above.z + dn.z);
            nv.w = (cur.z + rt   ) + (above.w + dn.w);

            if (EDGE) {
                int gy = gy0 + ybase + r;
                float my = (gy >= 1 && gy <= N - 2) ? 1.f : 0.f;
                nv.x *= my * mx0; nv.y *= my * mx1;
                nv.z *= my * mx2; nv.w *= my * mx3;
            }

            u[r]  = nv;
            above = cur;   // old value of this row feeds the next row
        }
    }
}

__device__ __forceinline__ void store_center(float4 (&u)[R], float* __restrict__ out,
                                             int warp, int lane, int x4,
                                             int gx0, int gy0, int ybase) {
    #pragma unroll
    for (int r = 0; r < R; r++) {
        int ty = ybase + r;
        if (ty < K || ty > BW - 1 - K) continue;
        int gy = gy0 + ty;
        if (gy >= N) continue;               // gy >= 0 guaranteed (ty >= K)
        float* row = out + (size_t)gy * N;
        int g = gx0 + x4;
        if (x4 + 0 >= K && x4 + 0 <= BW - 1 - K && g + 0 < N) row[g + 0] = u[r].x * SCALE;
        if (x4 + 1 >= K && x4 + 1 <= BW - 1 - K && g + 1 < N) row[g + 1] = u[r].y * SCALE;
        if (x4 + 2 >= K && x4 + 2 <= BW - 1 - K && g + 2 < N) row[g + 2] = u[r].z * SCALE;
        if (x4 + 3 >= K && x4 + 3 <= BW - 1 - K && g + 3 < N) row[g + 3] = u[r].w * SCALE;
    }
}

// ---- pass 0: compute x0 = exp(-50((X-.5)^2+(Y-.5)^2)) in-register, then K steps ----
__global__ __launch_bounds__(NTH, 2)
void jacobi_first(const float* __restrict__ X, const float* __restrict__ Y,
                  float* __restrict__ out) {
    __shared__ ExBuf ex[2];

    const int tid   = threadIdx.x;
    const int lane  = tid & 31;
    const int warp  = tid >> 5;
    const int x4    = lane * 4;
    const int gx0   = blockIdx.x * TX - K;
    const int gy0   = blockIdx.y * TX - K;
    const int ybase = warp * R;

    const bool tile_interior =
        (gx0 >= 1) && (gx0 + BW - 1 <= N - 2) &&
        (gy0 >= 1) && (gy0 + BW - 1 <= N - 2);

    float4 u[R];

    if (tile_interior) {
        #pragma unroll
        for (int r = 0; r < R; r++) {
            size_t base = (size_t)(gy0 + ybase + r) * N + gx0 + x4;
            #pragma unroll
            for (int e = 0; e < 4; e++) {
                float dx = X[base + e] - 0.5f;
                float dy = Y[base + e] - 0.5f;
                (&u[r].x)[e] = __expf(-50.0f * (dx * dx + dy * dy));
            }
        }
    } else {
        #pragma unroll
        for (int r = 0; r < R; r++) {
            int gy = gy0 + ybase + r;
            float4 v = make_float4(0.f, 0.f, 0.f, 0.f);
            if (gy >= 0 && gy < N) {
                size_t base = (size_t)gy * N;
                int g = gx0 + x4;
                #pragma unroll
                for (int e = 0; e < 4; e++) {
                    if (g + e >= 0 && g + e < N) {
                        float dx = X[base + g + e] - 0.5f;
                        float dy = Y[base + g + e] - 0.5f;
                        (&v.x)[e] = __expf(-50.0f * (dx * dx + dy * dy));
                    }
                }
            }
            u[r] = v;
        }
    }

    if (tile_interior)
        run_steps<false>(u, ex, warp, x4, gx0, gy0, ybase);
    else
        run_steps<true>(u, ex, warp, x4, gx0, gy0, ybase);

    store_center(u, out, warp, lane, x4, gx0, gy0, ybase);
}

// ---- passes 1..9: load prev state, K steps ----
__global__ __launch_bounds__(NTH, 2)
void jacobi_pass(const float* __restrict__ in, float* __restrict__ out) {
    __shared__ ExBuf ex[2];

    const int tid   = threadIdx.x;
    const int lane  = tid & 31;
    const int warp  = tid >> 5;
    const int x4    = lane * 4;
    const int gx0   = blockIdx.x * TX - K;
    const int gy0   = blockIdx.y * TX - K;
    const int ybase = warp * R;

    const bool tile_interior =
        (gx0 >= 1) && (gx0 + BW - 1 <= N - 2) &&
        (gy0 >= 1) && (gy0 + BW - 1 <= N - 2);

    float4 u[R];

    if (tile_interior) {
        #pragma unroll
        for (int r = 0; r < R; r++) {
            const float* p = in + (size_t)(gy0 + ybase + r) * N + gx0 + x4;
            u[r].x = p[0]; u[r].y = p[1]; u[r].z = p[2]; u[r].w = p[3];
        }
    } else {
        #pragma unroll
        for (int r = 0; r < R; r++) {
            int gy = gy0 + ybase + r;
            float4 v = make_float4(0.f, 0.f, 0.f, 0.f);
            if (gy >= 0 && gy < N) {
                const float* row = in + (size_t)gy * N;
                int g = gx0 + x4;
                if (g + 0 >= 0 && g + 0 < N) v.x = row[g + 0];
                if (g + 1 >= 0 && g + 1 < N) v.y = row[g + 1];
                if (g + 2 >= 0 && g + 2 < N) v.z = row[g + 2];
                if (g + 3 >= 0 && g + 3 < N) v.w = row[g + 3];
            }
            u[r] = v;
        }
    }

    if (tile_interior)
        run_steps<false>(u, ex, warp, x4, gx0, gy0, ybase);
    else
        run_steps<true>(u, ex, warp, x4, gx0, gy0, ybase);

    store_center(u, out, warp, lane, x4, gx0, gy0, ybase);
}

extern "C" void kernel_launch(void* const* d_in, const int* in_sizes, int n_in,
                              void* d_out, int out_size) {
    const float* X = (const float*)d_in[0];
    const float* Y = (const float*)d_in[1];
    float* A = (float*)d_out;
    float* B;
    cudaGetSymbolAddress((void**)&B, g_buf);

    dim3 grid(NBLK, NBLK);

    // pass 0 (fused init + 10 steps): (X,Y) -> B
    jacobi_first<<<grid, NTH>>>(X, Y, B);

    // passes 1..9: odd p: B -> A, even p: A -> B; p=9 ends in A (=d_out)
    for (int p = 1; p < 10; p++) {
        const float* src = (p & 1) ? B : A;
        float*       dst = (p & 1) ? A : B;
        jacobi_pass<<<grid, NTH>>>(src, dst);
    }
}